// round 2
// baseline (speedup 1.0000x reference)
#include <cuda_runtime.h>

#define BATCH   4096
#define PI2F    6.28318530717958647692f

// ---------------- scratch (device globals, no allocation) ----------------
__device__ float g_w1[32 * 9];                       // conv1 weights (16 gabor + 16 identity)
__device__ float g_out1[BATCH * 32 * 14 * 14];       // after conv1+relu+pool  (~103 MB)
__device__ float g_out2[BATCH * 64 * 7 * 7];         // after conv2+relu+pool  (~51 MB)
__device__ float g_fc1[BATCH * 128];                 // after fc1+relu

// ---------------- kernel 0: build conv1 weight bank ----------------
__global__ void k_gabor(const float* __restrict__ theta, const float* __restrict__ sigma,
                        const float* __restrict__ gamma, const float* __restrict__ lambd,
                        const float* __restrict__ psi) {
    int t = threadIdx.x;
    if (t >= 288) return;
    int c = t / 9, idx = t % 9;
    int i = idx / 3, j = idx % 3;       // i = ky (H), j = kx (W)
    float val;
    if (c < 16) {
        float xg = (float)(i - 1), yg = (float)(j - 1);
        float th = theta[c];
        float cth = cosf(th), sth = sinf(th);
        float xt =  xg * cth + yg * sth;
        float yt = -xg * sth + yg * cth;
        float sx = sigma[c];
        float sy = sigma[c] / gamma[c];
        float env = expf(-0.5f * (xt * xt / (sx * sx) + yt * yt / (sy * sy)));
        float car = cosf(PI2F * xt / lambd[c] + psi[c]);
        val = env * car;
    } else {
        val = (idx == 4) ? 1.0f : 0.0f;  // identity map, center tap
    }
    g_w1[c * 9 + idx] = val;
}

// ---------------- kernel 1: conv1 (3x3 pad1) + relu + maxpool2 ----------------
// one block per image; input image + 32x9 weights in smem
__global__ void k_conv1(const float* __restrict__ x) {
    __shared__ float si[28 * 28];
    __shared__ float sw[32 * 9];
    int b = blockIdx.x;
    for (int i = threadIdx.x; i < 784; i += 256) si[i] = x[b * 784 + i];
    for (int i = threadIdx.x; i < 288; i += 256) sw[i] = g_w1[i];
    __syncthreads();

    for (int o = threadIdx.x; o < 32 * 14 * 14; o += 256) {
        int c = o / 196, p = o % 196;
        int py = p / 14, px = p % 14;
        float m = 0.0f;   // relu outputs are >= 0, so 0 is a valid identity for the max
        #pragma unroll
        for (int dy = 0; dy < 2; dy++) {
            #pragma unroll
            for (int dx = 0; dx < 2; dx++) {
                int y = 2 * py + dy, xx = 2 * px + dx;
                float acc = 0.0f;
                #pragma unroll
                for (int ky = 0; ky < 3; ky++) {
                    int yy = y + ky - 1;
                    if (yy < 0 || yy >= 28) continue;
                    #pragma unroll
                    for (int kx = 0; kx < 3; kx++) {
                        int xc = xx + kx - 1;
                        if (xc < 0 || xc >= 28) continue;
                        acc = fmaf(si[yy * 28 + xc], sw[c * 9 + ky * 3 + kx], acc);
                    }
                }
                m = fmaxf(m, acc);
            }
        }
        g_out1[b * 6272 + o] = m;
    }
}

// ---------------- kernel 2: conv2 (64x32x3x3 pad1) + bias + relu + maxpool2 ----------------
// one block per image. smem: padded input (32 x 16 x 16) + full weight tensor (64*32*9).
// 392 threads = 49 pooled positions x 8 oc-groups; each thread owns 8 oc x 4 pool positions.
#define C2_SI_FLOATS  (32 * 16 * 16)     // 8192
#define C2_SW_FLOATS  (64 * 32 * 9)      // 18432
#define C2_SMEM_BYTES ((C2_SI_FLOATS + C2_SW_FLOATS) * 4)   // 106496

__global__ void k_conv2(const float* __restrict__ w, const float* __restrict__ bias) {
    extern __shared__ float smem2[];
    float* si  = smem2;                   // padded input, zero border
    float* swt = smem2 + C2_SI_FLOATS;    // weights OIHW
    int b   = blockIdx.x;
    int tid = threadIdx.x;                // 392

    for (int i = tid; i < C2_SI_FLOATS; i += 392) si[i] = 0.0f;
    for (int i = tid; i < C2_SW_FLOATS; i += 392) swt[i] = w[i];
    __syncthreads();
    for (int i = tid; i < 32 * 196; i += 392) {
        int ic = i / 196, p = i % 196;
        int y = p / 14, xx = p % 14;
        si[ic * 256 + (y + 1) * 16 + (xx + 1)] = g_out1[b * 6272 + i];
    }
    __syncthreads();

    int p   = tid % 49;
    int grp = tid / 49;                   // 0..7 -> oc [grp*8, grp*8+8)
    int py  = p / 7, px = p % 7;

    float acc[8][4];
    #pragma unroll
    for (int o = 0; o < 8; o++)
        #pragma unroll
        for (int q = 0; q < 4; q++) acc[o][q] = 0.0f;

    #pragma unroll 1
    for (int ic = 0; ic < 32; ic++) {
        // 4x4 input patch covering the 2x2 conv windows of this pooled output
        float patch[4][4];
        const float* sp = si + ic * 256 + (2 * py) * 16 + 2 * px;
        #pragma unroll
        for (int r = 0; r < 4; r++)
            #pragma unroll
            for (int cidx = 0; cidx < 4; cidx++)
                patch[r][cidx] = sp[r * 16 + cidx];

        #pragma unroll
        for (int o = 0; o < 8; o++) {
            const float* wp = swt + ((grp * 8 + o) * 32 + ic) * 9;
            float wv[9];
            #pragma unroll
            for (int q = 0; q < 9; q++) wv[q] = wp[q];
            #pragma unroll
            for (int dy = 0; dy < 2; dy++)
                #pragma unroll
                for (int dx = 0; dx < 2; dx++) {
                    float a = acc[o][dy * 2 + dx];
                    #pragma unroll
                    for (int ky = 0; ky < 3; ky++)
                        #pragma unroll
                        for (int kx = 0; kx < 3; kx++)
                            a = fmaf(wv[ky * 3 + kx], patch[dy + ky][dx + kx], a);
                    acc[o][dy * 2 + dx] = a;
                }
        }
    }

    #pragma unroll
    for (int o = 0; o < 8; o++) {
        int oc = grp * 8 + o;
        float bv = bias[oc];
        float m = 0.0f;
        #pragma unroll
        for (int q = 0; q < 4; q++) m = fmaxf(m, acc[o][q] + bv);
        g_out2[b * 3136 + oc * 49 + p] = m;
    }
}

// ---------------- kernel 3: fc1 GEMM  (4096x3136) @ (3136x128)^T + relu ----------------
// BM=32, BN=128, BK=32; 128 threads; each thread: 4x8 micro-tile
__global__ void k_fc1(const float* __restrict__ W, const float* __restrict__ bvec) {
    __shared__ float aT[32][36];      // [kk][row], padded to 36 for alignment/conflicts
    __shared__ float bT[32][128];     // [kk][n]
    int bm  = blockIdx.x * 32;
    int tid = threadIdx.x;            // 128
    int ty = tid / 16, tx = tid % 16;

    float acc[4][8];
    #pragma unroll
    for (int r = 0; r < 4; r++)
        #pragma unroll
        for (int c = 0; c < 8; c++) acc[r][c] = 0.0f;

    for (int k0 = 0; k0 < 3136; k0 += 32) {
        #pragma unroll
        for (int i = 0; i < 8; i++) {
            int idx = tid + i * 128;
            int row = idx / 32, kk = idx % 32;
            aT[kk][row] = g_out2[(bm + row) * 3136 + k0 + kk];
        }
        {
            const float4* wrow = (const float4*)(W + tid * 3136 + k0);  // n = tid
            #pragma unroll
            for (int i = 0; i < 8; i++) {
                float4 v = wrow[i];
                int kk = i * 4;
                bT[kk + 0][tid] = v.x;
                bT[kk + 1][tid] = v.y;
                bT[kk + 2][tid] = v.z;
                bT[kk + 3][tid] = v.w;
            }
        }
        __syncthreads();

        #pragma unroll
        for (int kk = 0; kk < 32; kk++) {
            float ra[4], rb[8];
            #pragma unroll
            for (int r = 0; r < 4; r++) ra[r] = aT[kk][ty * 4 + r];
            #pragma unroll
            for (int c = 0; c < 8; c++) rb[c] = bT[kk][tx * 8 + c];
            #pragma unroll
            for (int r = 0; r < 4; r++)
                #pragma unroll
                for (int c = 0; c < 8; c++)
                    acc[r][c] = fmaf(ra[r], rb[c], acc[r][c]);
        }
        __syncthreads();
    }

    #pragma unroll
    for (int r = 0; r < 4; r++) {
        int row = bm + ty * 4 + r;
        #pragma unroll
        for (int c = 0; c < 8; c++) {
            int n = tx * 8 + c;
            float v = acc[r][c] + bvec[n];
            g_fc1[row * 128 + n] = fmaxf(v, 0.0f);
        }
    }
}

// ---------------- kernel 4: fc2  (4096x128) @ (128x10)^T -> d_out ----------------
__global__ void k_fc2(const float* __restrict__ W2, const float* __restrict__ b2,
                      float* __restrict__ out) {
    __shared__ float sw[10 * 128];
    __shared__ float sb[10];
    int tid = threadIdx.x;
    for (int i = tid; i < 1280; i += 256) sw[i] = W2[i];
    if (tid < 10) sb[tid] = b2[tid];
    __syncthreads();

    int idx = blockIdx.x * 256 + tid;
    if (idx >= BATCH * 10) return;
    int b = idx / 10, n = idx % 10;
    const float* arow = g_fc1 + b * 128;
    const float* wrow = sw + n * 128;
    float acc = 0.0f;
    #pragma unroll
    for (int k = 0; k < 128; k++) acc = fmaf(arow[k], wrow[k], acc);
    out[b * 10 + n] = acc + sb[n];
}

// ---------------- launch ----------------
extern "C" void kernel_launch(void* const* d_in, const int* in_sizes, int n_in,
                              void* d_out, int out_size) {
    const float* x       = (const float*)d_in[0];
    const float* theta   = (const float*)d_in[1];
    const float* sigma   = (const float*)d_in[2];
    const float* gamma   = (const float*)d_in[3];
    const float* lambd   = (const float*)d_in[4];
    const float* psi     = (const float*)d_in[5];
    const float* conv2_w = (const float*)d_in[6];
    const float* conv2_b = (const float*)d_in[7];
    const float* fc1_w   = (const float*)d_in[8];
    const float* fc1_b   = (const float*)d_in[9];
    const float* fc2_w   = (const float*)d_in[10];
    const float* fc2_b   = (const float*)d_in[11];
    float* out = (float*)d_out;

    cudaFuncSetAttribute(k_conv2, cudaFuncAttributeMaxDynamicSharedMemorySize, C2_SMEM_BYTES);

    k_gabor<<<1, 288>>>(theta, sigma, gamma, lambd, psi);
    k_conv1<<<BATCH, 256>>>(x);
    k_conv2<<<BATCH, 392, C2_SMEM_BYTES>>>(conv2_w, conv2_b);
    k_fc1<<<BATCH / 32, 128>>>(fc1_w, fc1_b);
    k_fc2<<<(BATCH * 10 + 255) / 256, 256>>>(fc2_w, fc2_b, out);
}

// round 4
// speedup vs baseline: 1.4470x; 1.4470x over previous
#include <cuda_runtime.h>

#define BATCH 4096
#define PI2F  6.28318530717958647692f

typedef unsigned long long u64;

// ---------------- f32x2 helpers ----------------
__device__ __forceinline__ u64 pk2(float lo, float hi) {
    u64 r; asm("mov.b64 %0, {%1,%2};" : "=l"(r) : "f"(lo), "f"(hi)); return r;
}
__device__ __forceinline__ void upk2(u64 v, float& lo, float& hi) {
    asm("mov.b64 {%0,%1}, %2;" : "=f"(lo), "=f"(hi) : "l"(v));
}
__device__ __forceinline__ u64 fma2(u64 a, u64 b, u64 c) {
    u64 d; asm("fma.rn.f32x2 %0, %1, %2, %3;" : "=l"(d) : "l"(a), "l"(b), "l"(c)); return d;
}

// ---------------- scratch ----------------
__device__ float g_w1[32 * 9];
__device__ float g_out1[BATCH * 32 * 14 * 14];   // conv1+pool out, NCHW
__device__ float g_out2[BATCH * 64 * 7 * 7];     // conv2+pool out
__device__ float g_fc1p[4][BATCH * 128];         // fc1 split-K partials

// ---------------- kernel 0: gabor weights ----------------
__global__ void k_gabor(const float* __restrict__ theta, const float* __restrict__ sigma,
                        const float* __restrict__ gamma, const float* __restrict__ lambd,
                        const float* __restrict__ psi) {
    int t = threadIdx.x;
    if (t >= 288) return;
    int c = t / 9, idx = t % 9;
    int i = idx / 3, j = idx % 3;
    float val;
    if (c < 16) {
        float xg = (float)(i - 1), yg = (float)(j - 1);
        float th = theta[c];
        float cth = cosf(th), sth = sinf(th);
        float xt =  xg * cth + yg * sth;
        float yt = -xg * sth + yg * cth;
        float sx = sigma[c];
        float sy = sigma[c] / gamma[c];
        float env = expf(-0.5f * (xt * xt / (sx * sx) + yt * yt / (sy * sy)));
        float car = cosf(PI2F * xt / lambd[c] + psi[c]);
        val = env * car;
    } else {
        val = (idx == 4) ? 1.0f : 0.0f;
    }
    g_w1[c * 9 + idx] = val;
}

// ---------------- kernel 1: conv1 + relu + maxpool2 (branch-free padded smem) ----------------
__global__ void k_conv1(const float* __restrict__ x) {
    __shared__ float si[30 * 30];
    __shared__ float sw[32 * 9];
    int b = blockIdx.x;
    for (int i = threadIdx.x; i < 900; i += 256) si[i] = 0.0f;
    for (int i = threadIdx.x; i < 288; i += 256) sw[i] = g_w1[i];
    __syncthreads();
    for (int i = threadIdx.x; i < 784; i += 256) {
        int y = i / 28, xx = i % 28;
        si[(y + 1) * 30 + xx + 1] = x[b * 784 + i];
    }
    __syncthreads();

    for (int o = threadIdx.x; o < 32 * 196; o += 256) {
        int c = o / 196, p = o % 196;
        int py = p / 14, px = p % 14;
        const float* wc = sw + c * 9;
        float m = 0.0f;
        #pragma unroll
        for (int dy = 0; dy < 2; dy++) {
            #pragma unroll
            for (int dx = 0; dx < 2; dx++) {
                const float* sp = si + (2 * py + dy) * 30 + (2 * px + dx);
                float acc = 0.0f;
                #pragma unroll
                for (int ky = 0; ky < 3; ky++)
                    #pragma unroll
                    for (int kx = 0; kx < 3; kx++)
                        acc = fmaf(sp[ky * 30 + kx], wc[ky * 3 + kx], acc);
                m = fmaxf(m, acc);
            }
        }
        g_out1[b * 6272 + o] = m;
    }
}

// ---------------- kernel 2: conv2 + bias + relu + maxpool2, f32x2 over oc-pairs ----------------
// Persistent blocks. smem: padded input 32x16x16 fp32 + transposed weights [ic][q][oc].
// 224 threads = 7 warps; warp = pooled row py, lane = oc-group g (oc 2g,2g+1).
#define C2T 224
#define C2_SMEM_BYTES ((8192 + 18432) * 4)   // 106496

__global__ void __launch_bounds__(C2T, 2) k_conv2(const float* __restrict__ w,
                                                  const float* __restrict__ bias) {
    extern __shared__ float sm[];
    float* si = sm;           // [ic][16][16], zero border
    float* wT = sm + 8192;    // [(ic*9+q)*64 + oc]
    int tid = threadIdx.x;

    for (int i = tid; i < 18432; i += C2T) {
        int oc = i / 288, r = i % 288;          // r = ic*9 + q
        wT[r * 64 + oc] = w[i];
    }
    for (int i = tid; i < 8192; i += C2T) si[i] = 0.0f;

    int py = tid >> 5;        // 0..6
    int g  = tid & 31;        // oc pair (2g, 2g+1)
    float bv0 = bias[2 * g], bv1 = bias[2 * g + 1];
    __syncthreads();

    for (int img = blockIdx.x; img < BATCH; img += gridDim.x) {
        for (int i = tid; i < 6272; i += C2T) {
            int ic = i / 196, p = i % 196;
            si[ic * 256 + (p / 14 + 1) * 16 + (p % 14) + 1] = g_out1[img * 6272 + i];
        }
        __syncthreads();

        u64 acc[2][14];
        #pragma unroll
        for (int dy = 0; dy < 2; dy++)
            #pragma unroll
            for (int c = 0; c < 14; c++) acc[dy][c] = 0ULL;

        #pragma unroll 1
        for (int ic = 0; ic < 32; ic++) {
            // weight pairs over (oc, oc+1): aligned LDS.64, conflict-free
            const float* wp = wT + ic * 576 + 2 * g;
            u64 wv[9];
            #pragma unroll
            for (int q = 0; q < 9; q++) wv[q] = *(const u64*)(wp + q * 64);

            const float* rp = si + ic * 256 + (2 * py) * 16;
            #pragma unroll
            for (int ir = 0; ir < 4; ir++) {
                // load padded row (warp-uniform -> broadcast)
                float rr[16];
                const float4* r4 = (const float4*)(rp + ir * 16);
                #pragma unroll
                for (int q = 0; q < 4; q++) {
                    float4 v = r4[q];
                    rr[q * 4 + 0] = v.x; rr[q * 4 + 1] = v.y;
                    rr[q * 4 + 2] = v.z; rr[q * 4 + 3] = v.w;
                }
                u64 d[16];
                #pragma unroll
                for (int c = 0; c < 16; c++) d[c] = pk2(rr[c], rr[c]);

                #pragma unroll
                for (int dy = 0; dy < 2; dy++) {
                    int ky = ir - dy;
                    if (ky < 0 || ky > 2) continue;
                    #pragma unroll
                    for (int kx = 0; kx < 3; kx++) {
                        u64 wq = wv[ky * 3 + kx];
                        #pragma unroll
                        for (int c = 0; c < 14; c++)
                            acc[dy][c] = fma2(d[c + kx], wq, acc[dy][c]);
                    }
                }
            }
        }

        // epilogue: bias + relu + 2x2 maxpool
        #pragma unroll
        for (int px = 0; px < 7; px++) {
            float a0, a1, b0, b1, c0, c1, e0, e1;
            upk2(acc[0][2 * px],     a0, a1);
            upk2(acc[0][2 * px + 1], b0, b1);
            upk2(acc[1][2 * px],     c0, c1);
            upk2(acc[1][2 * px + 1], e0, e1);
            float m0 = fmaxf(fmaxf(a0, b0), fmaxf(c0, e0));
            float m1 = fmaxf(fmaxf(a1, b1), fmaxf(c1, e1));
            int base = img * 3136 + py * 7 + px;
            g_out2[base + (2 * g) * 49]     = fmaxf(m0 + bv0, 0.0f);
            g_out2[base + (2 * g + 1) * 49] = fmaxf(m1 + bv1, 0.0f);
        }
        __syncthreads();
    }
}

// ---------------- kernel 3: fc1 split-K GEMM, f32x2 ----------------
// grid (128, 4): BM=32 rows, K chunk 784. 128 threads; thread tile 4 rows x 8 cols.
__global__ void k_fc1(const float* __restrict__ W) {
    __shared__ float aT[16][33];
    __shared__ float bT[16][128];
    int bm   = blockIdx.x * 32;
    int koff = blockIdx.y * 784;
    int tid  = threadIdx.x;
    int ty = tid / 16, tx = tid % 16;

    u64 acc[4][4];
    #pragma unroll
    for (int r = 0; r < 4; r++)
        #pragma unroll
        for (int c = 0; c < 4; c++) acc[r][c] = 0ULL;

    for (int k0 = 0; k0 < 784; k0 += 16) {
        #pragma unroll
        for (int i = 0; i < 4; i++) {
            int e = tid + i * 128;
            int row = e >> 4, kk = e & 15;
            aT[kk][row] = g_out2[(bm + row) * 3136 + koff + k0 + kk];
        }
        const float4* wr = (const float4*)(W + tid * 3136 + koff + k0);
        #pragma unroll
        for (int i = 0; i < 4; i++) {
            float4 v = wr[i];
            bT[i * 4 + 0][tid] = v.x; bT[i * 4 + 1][tid] = v.y;
            bT[i * 4 + 2][tid] = v.z; bT[i * 4 + 3][tid] = v.w;
        }
        __syncthreads();

        #pragma unroll
        for (int kk = 0; kk < 16; kk++) {
            u64 ra[4], rb[4];
            #pragma unroll
            for (int r = 0; r < 4; r++) { float a = aT[kk][ty * 4 + r]; ra[r] = pk2(a, a); }
            #pragma unroll
            for (int c = 0; c < 4; c++) rb[c] = *(const u64*)&bT[kk][tx * 8 + 2 * c];
            #pragma unroll
            for (int r = 0; r < 4; r++)
                #pragma unroll
                for (int c = 0; c < 4; c++)
                    acc[r][c] = fma2(ra[r], rb[c], acc[r][c]);
        }
        __syncthreads();
    }

    float* outp = &g_fc1p[blockIdx.y][0];
    #pragma unroll
    for (int r = 0; r < 4; r++) {
        int row = bm + ty * 4 + r;
        #pragma unroll
        for (int c = 0; c < 4; c++) {
            float lo, hi; upk2(acc[r][c], lo, hi);
            outp[row * 128 + tx * 8 + 2 * c]     = lo;
            outp[row * 128 + tx * 8 + 2 * c + 1] = hi;
        }
    }
}

// ---------------- kernel 4: combine partials + bias + relu, then fc2 ----------------
// 320 threads = 10 warps; one block per image; warp n computes output n via shuffle reduce.
__global__ void k_fc2(const float* __restrict__ W2, const float* __restrict__ fc1b,
                      const float* __restrict__ b2, float* __restrict__ out) {
    __shared__ float h[128];
    __shared__ float sw[1280];
    int b = blockIdx.x, tid = threadIdx.x;
    for (int i = tid; i < 1280; i += 320) sw[i] = W2[i];
    if (tid < 128) {
        float s = fc1b[tid];
        #pragma unroll
        for (int sp = 0; sp < 4; sp++) s += g_fc1p[sp][b * 128 + tid];
        h[tid] = fmaxf(s, 0.0f);
    }
    __syncthreads();
    int wrp = tid / 32, l = tid % 32;
    float a = 0.0f;
    #pragma unroll
    for (int i = 0; i < 4; i++) a = fmaf(h[l + 32 * i], sw[wrp * 128 + l + 32 * i], a);
    #pragma unroll
    for (int off = 16; off; off >>= 1) a += __shfl_xor_sync(0xffffffff, a, off);
    if (l == 0) out[b * 10 + wrp] = a + b2[wrp];
}

// ---------------- launch ----------------
extern "C" void kernel_launch(void* const* d_in, const int* in_sizes, int n_in,
                              void* d_out, int out_size) {
    const float* x       = (const float*)d_in[0];
    const float* theta   = (const float*)d_in[1];
    const float* sigma   = (const float*)d_in[2];
    const float* gamma   = (const float*)d_in[3];
    const float* lambd   = (const float*)d_in[4];
    const float* psi     = (const float*)d_in[5];
    const float* conv2_w = (const float*)d_in[6];
    const float* conv2_b = (const float*)d_in[7];
    const float* fc1_w   = (const float*)d_in[8];
    const float* fc1_b   = (const float*)d_in[9];
    const float* fc2_w   = (const float*)d_in[10];
    const float* fc2_b   = (const float*)d_in[11];
    float* out = (float*)d_out;

    cudaFuncSetAttribute(k_conv2, cudaFuncAttributeMaxDynamicSharedMemorySize, C2_SMEM_BYTES);

    k_gabor<<<1, 288>>>(theta, sigma, gamma, lambd, psi);
    k_conv1<<<BATCH, 256>>>(x);
    k_conv2<<<304, C2T, C2_SMEM_BYTES>>>(conv2_w, conv2_b);
    dim3 g1(128, 4);
    k_fc1<<<g1, 128>>>(fc1_w);
    k_fc2<<<BATCH, 320>>>(fc2_w, fc1_b, fc2_b, out);
}

// round 10
// speedup vs baseline: 2.8906x; 1.9976x over previous
#include <cuda_runtime.h>
#include <cuda_fp16.h>
#include <cstdint>

#define BATCH 4096
#define PI2F  6.28318530717958647692f

typedef unsigned long long u64;

// ---------------- f32x2 helpers ----------------
__device__ __forceinline__ u64 pk2(float lo, float hi) {
    u64 r; asm("mov.b64 %0, {%1,%2};" : "=l"(r) : "f"(lo), "f"(hi)); return r;
}
__device__ __forceinline__ void upk2(u64 v, float& lo, float& hi) {
    asm("mov.b64 {%0,%1}, %2;" : "=f"(lo), "=f"(hi) : "l"(v));
}
__device__ __forceinline__ u64 fma2(u64 a, u64 b, u64 c) {
    u64 d; asm("fma.rn.f32x2 %0, %1, %2, %3;" : "=l"(d) : "l"(a), "l"(b), "l"(c)); return d;
}

// ---------------- HMMA m16n8k16 (f16 x f16 -> f32) ----------------
#define MMA16816(d, a0, a1, a2, a3, b0, b1) \
    asm volatile("mma.sync.aligned.m16n8k16.row.col.f32.f16.f16.f32 " \
        "{%0,%1,%2,%3}, {%4,%5,%6,%7}, {%8,%9}, {%0,%1,%2,%3};" \
        : "+f"((d)[0]), "+f"((d)[1]), "+f"((d)[2]), "+f"((d)[3]) \
        : "r"(a0), "r"(a1), "r"(a2), "r"(a3), "r"(b0), "r"(b1))

// ---------------- scratch ----------------
__device__ float g_w1[32 * 9];
__device__ float g_out1[BATCH * 32 * 14 * 14];
__device__ float g_out2[BATCH * 64 * 7 * 7];
__device__ float g_fc1p[7][BATCH * 128];

// ---------------- kernel 0: gabor weights ----------------
__global__ void k_gabor(const float* __restrict__ theta, const float* __restrict__ sigma,
                        const float* __restrict__ gamma, const float* __restrict__ lambd,
                        const float* __restrict__ psi) {
    int t = threadIdx.x;
    if (t >= 288) return;
    int c = t / 9, idx = t % 9;
    int i = idx / 3, j = idx % 3;
    float val;
    if (c < 16) {
        float xg = (float)(i - 1), yg = (float)(j - 1);
        float th = theta[c];
        float cth = cosf(th), sth = sinf(th);
        float xt =  xg * cth + yg * sth;
        float yt = -xg * sth + yg * cth;
        float sx = sigma[c];
        float sy = sigma[c] / gamma[c];
        float env = expf(-0.5f * (xt * xt / (sx * sx) + yt * yt / (sy * sy)));
        float car = cosf(PI2F * xt / lambd[c] + psi[c]);
        val = env * car;
    } else {
        val = (idx == 4) ? 1.0f : 0.0f;
    }
    g_w1[c * 9 + idx] = val;
}

// ---------------- kernel 1: conv1 + relu + maxpool2, f32x2 channel pairs ----------------
__global__ void k_conv1(const float* __restrict__ x) {
    __shared__ float si[30 * 30];
    __shared__ float sw2[9 * 32];           // [q][c] so channel pairs are LDS.64
    int b = blockIdx.x;
    for (int i = threadIdx.x; i < 900; i += 256) si[i] = 0.0f;
    for (int i = threadIdx.x; i < 288; i += 256) {
        int c = i / 9, q = i % 9;
        sw2[q * 32 + c] = g_w1[i];
    }
    __syncthreads();
    for (int i = threadIdx.x; i < 784; i += 256) {
        int y = i / 28, xx = i % 28;
        si[(y + 1) * 30 + xx + 1] = x[b * 784 + i];
    }
    __syncthreads();

    for (int o = threadIdx.x; o < 16 * 196; o += 256) {
        int cp = o / 196, p = o % 196;       // channel pair (2cp, 2cp+1)
        int py = p / 14, px = p % 14;

        u64 w2[9];
        #pragma unroll
        for (int q = 0; q < 9; q++) w2[q] = *(const u64*)&sw2[q * 32 + 2 * cp];

        float rr[4][4];
        const float* sp = si + (2 * py) * 30 + 2 * px;
        #pragma unroll
        for (int r = 0; r < 4; r++)
            #pragma unroll
            for (int c = 0; c < 4; c++) rr[r][c] = sp[r * 30 + c];

        float m0 = 0.0f, m1 = 0.0f;
        #pragma unroll
        for (int dy = 0; dy < 2; dy++)
            #pragma unroll
            for (int dx = 0; dx < 2; dx++) {
                u64 a = 0ULL;
                #pragma unroll
                for (int ky = 0; ky < 3; ky++)
                    #pragma unroll
                    for (int kx = 0; kx < 3; kx++) {
                        float v = rr[dy + ky][dx + kx];
                        a = fma2(pk2(v, v), w2[ky * 3 + kx], a);
                    }
                float lo, hi; upk2(a, lo, hi);
                m0 = fmaxf(m0, lo);
                m1 = fmaxf(m1, hi);
            }
        g_out1[b * 6272 + (2 * cp) * 196 + p]     = m0;
        g_out1[b * 6272 + (2 * cp + 1) * 196 + p] = m1;
    }
}

// ---------------- kernel 2: conv2 via HMMA shift-decomposition ----------------
// Input as padded HWC fp16 [292 rows][36 halves] (rows = py*16+px, zero borders/pad).
// 3x3 conv = 9 shifted GEMMs of K=32. W fp16 [64 oc][296 halves], k = q*32+ic.
// 7 compute warps: warp w owns M-tiles 2w,2w+1 (m16 each, 224 pos) x all 8 n8-tiles.
#define C2_THREADS 224
#define SM_BIAS 0
#define SM_IN   256                 // 292*36 halves = 21024 B
#define SM_W    21312               // 64*296 halves = 37888 B
#define SM_POOL 59264               // 224*66 floats = 59136 B
#define C2_SMEM 118400

__global__ void __launch_bounds__(C2_THREADS, 1)
k_conv2_mma(const float* __restrict__ w, const float* __restrict__ bias) {
    extern __shared__ char sm[];
    float* biasS = (float*)(sm + SM_BIAS);
    __half* wH   = (__half*)(sm + SM_W);
    float* pool  = (float*)(sm + SM_POOL);
    uint32_t* inw       = (uint32_t*)(sm + SM_IN);
    const uint32_t* ww  = (const uint32_t*)(sm + SM_W);
    int tid = threadIdx.x, warp = tid >> 5, lane = tid & 31;
    int grp = lane >> 2, tig = lane & 3;

    if (tid < 64) biasS[tid] = bias[tid];
    for (int i = tid; i < 292 * 18; i += C2_THREADS) inw[i] = 0u;
    for (int i = tid; i < 64 * 288; i += C2_THREADS) {
        int oc = i / 288, r = i % 288, ic = r / 9, q = r % 9;
        wH[oc * 296 + q * 32 + ic] = __float2half_rn(w[i]);
    }
    __syncthreads();

    // per-thread A row bases (shift-0 padded row index), pad positions -> zero region
    int rb[4];
    {
        int t0 = 2 * warp;
        int ps[4] = { t0 * 16 + grp, t0 * 16 + grp + 8,
                      t0 * 16 + 16 + grp, t0 * 16 + 16 + grp + 8 };
        #pragma unroll
        for (int j = 0; j < 4; j++)
            rb[j] = (ps[j] < 196) ? ((ps[j] / 14) * 16 + (ps[j] % 14)) * 18
                                  : 256 * 18;
    }

    for (int img = blockIdx.x; img < BATCH; img += gridDim.x) {
        // ---- input NCHW fp32 -> padded HWC fp16 ----
        const float* src = g_out1 + img * 6272;
        for (int e = tid; e < 16 * 196; e += C2_THREADS) {
            int ic2 = e / 196, p = e % 196;
            float v0 = src[(2 * ic2) * 196 + p];
            float v1 = src[(2 * ic2 + 1) * 196 + p];
            int row = (p / 14 + 1) * 16 + (p % 14) + 1;
            uint32_t pk = (uint32_t)__half_as_ushort(__float2half_rn(v0))
                        | ((uint32_t)__half_as_ushort(__float2half_rn(v1)) << 16);
            inw[row * 18 + ic2] = pk;
        }
        __syncthreads();

        if (warp < 7) {
            float acc[2][8][4];
            #pragma unroll
            for (int ti = 0; ti < 2; ti++)
                #pragma unroll
                for (int nt = 0; nt < 8; nt++)
                    #pragma unroll
                    for (int q = 0; q < 4; q++) acc[ti][nt][q] = 0.0f;

            #pragma unroll 1
            for (int ky = 0; ky < 3; ky++) {
                #pragma unroll 1
                for (int kx = 0; kx < 3; kx++) {
                    int sh = (ky * 16 + kx) * 18;
                    int wq = (ky * 3 + kx) * 16;
                    #pragma unroll
                    for (int s = 0; s < 2; s++) {
                        int ao = sh + s * 8 + tig;
                        uint32_t a0 = inw[rb[0] + ao];
                        uint32_t a1 = inw[rb[1] + ao];
                        uint32_t a2 = inw[rb[0] + ao + 4];
                        uint32_t a3 = inw[rb[1] + ao + 4];
                        uint32_t a4 = inw[rb[2] + ao];
                        uint32_t a5 = inw[rb[3] + ao];
                        uint32_t a6 = inw[rb[2] + ao + 4];
                        uint32_t a7 = inw[rb[3] + ao + 4];
                        int wo = wq + s * 8 + tig;
                        uint32_t bA[8], bB[8];
                        #pragma unroll
                        for (int nt = 0; nt < 8; nt++) {
                            int n = nt * 8 + grp;
                            bA[nt] = ww[n * 148 + wo];
                            bB[nt] = ww[n * 148 + wo + 4];
                        }
                        #pragma unroll
                        for (int nt = 0; nt < 8; nt++) {
                            MMA16816(acc[0][nt], a0, a1, a2, a3, bA[nt], bB[nt]);
                            MMA16816(acc[1][nt], a4, a5, a6, a7, bA[nt], bB[nt]);
                        }
                    }
                }
            }

            // ---- D frags -> pool smem [pos][66] ----
            #pragma unroll
            for (int ti = 0; ti < 2; ti++) {
                int pr0 = (2 * warp + ti) * 16 + grp;
                #pragma unroll
                for (int nt = 0; nt < 8; nt++) {
                    int cb = nt * 8 + 2 * tig;
                    *(float2*)&pool[pr0 * 66 + cb]       = make_float2(acc[ti][nt][0], acc[ti][nt][1]);
                    *(float2*)&pool[(pr0 + 8) * 66 + cb] = make_float2(acc[ti][nt][2], acc[ti][nt][3]);
                }
            }
        }
        __syncthreads();

        // ---- bias + relu + 2x2 maxpool -> g_out2 ----
        float* dst = g_out2 + img * 3136;
        for (int e = tid; e < 3136; e += C2_THREADS) {
            int oc = e / 49, pq = e % 49;
            int py = pq / 7, px = pq % 7;
            int p00 = (2 * py) * 14 + 2 * px;
            float m = fmaxf(fmaxf(pool[p00 * 66 + oc],        pool[(p00 + 1) * 66 + oc]),
                            fmaxf(pool[(p00 + 14) * 66 + oc], pool[(p00 + 15) * 66 + oc]));
            dst[oc * 49 + pq] = fmaxf(m + biasS[oc], 0.0f);
        }
        __syncthreads();
    }
}

// ---------------- kernel 3: fc1 split-K(7) GEMM, f32x2 ----------------
__global__ void k_fc1(const float* __restrict__ W) {
    __shared__ float aT[16][33];
    __shared__ float bT[16][128];
    int bm   = blockIdx.x * 32;
    int koff = blockIdx.y * 448;
    int tid  = threadIdx.x;
    int ty = tid / 16, tx = tid % 16;

    u64 acc[4][4];
    #pragma unroll
    for (int r = 0; r < 4; r++)
        #pragma unroll
        for (int c = 0; c < 4; c++) acc[r][c] = 0ULL;

    for (int k0 = 0; k0 < 448; k0 += 16) {
        #pragma unroll
        for (int i = 0; i < 4; i++) {
            int e = tid + i * 128;
            int row = e >> 4, kk = e & 15;
            aT[kk][row] = g_out2[(bm + row) * 3136 + koff + k0 + kk];
        }
        const float4* wr = (const float4*)(W + tid * 3136 + koff + k0);
        #pragma unroll
        for (int i = 0; i < 4; i++) {
            float4 v = wr[i];
            bT[i * 4 + 0][tid] = v.x; bT[i * 4 + 1][tid] = v.y;
            bT[i * 4 + 2][tid] = v.z; bT[i * 4 + 3][tid] = v.w;
        }
        __syncthreads();

        #pragma unroll
        for (int kk = 0; kk < 16; kk++) {
            u64 ra[4], rbv[4];
            #pragma unroll
            for (int r = 0; r < 4; r++) { float a = aT[kk][ty * 4 + r]; ra[r] = pk2(a, a); }
            #pragma unroll
            for (int c = 0; c < 4; c++) rbv[c] = *(const u64*)&bT[kk][tx * 8 + 2 * c];
            #pragma unroll
            for (int r = 0; r < 4; r++)
                #pragma unroll
                for (int c = 0; c < 4; c++)
                    acc[r][c] = fma2(ra[r], rbv[c], acc[r][c]);
        }
        __syncthreads();
    }

    float* outp = &g_fc1p[blockIdx.y][0];
    #pragma unroll
    for (int r = 0; r < 4; r++) {
        int row = bm + ty * 4 + r;
        #pragma unroll
        for (int c = 0; c < 4; c++) {
            float lo, hi; upk2(acc[r][c], lo, hi);
            outp[row * 128 + tx * 8 + 2 * c]     = lo;
            outp[row * 128 + tx * 8 + 2 * c + 1] = hi;
        }
    }
}

// ---------------- kernel 4: combine 7 partials + bias + relu + fc2 ----------------
__global__ void k_fc2(const float* __restrict__ W2, const float* __restrict__ fc1b,
                      const float* __restrict__ b2, float* __restrict__ out) {
    __shared__ float h[128];
    __shared__ float sw[1280];
    int b = blockIdx.x, tid = threadIdx.x;
    for (int i = tid; i < 1280; i += 320) sw[i] = W2[i];
    if (tid < 128) {
        float s = fc1b[tid];
        #pragma unroll
        for (int sp = 0; sp < 7; sp++) s += g_fc1p[sp][b * 128 + tid];
        h[tid] = fmaxf(s, 0.0f);
    }
    __syncthreads();
    int wrp = tid / 32, l = tid % 32;
    float a = 0.0f;
    #pragma unroll
    for (int i = 0; i < 4; i++) a = fmaf(h[l + 32 * i], sw[wrp * 128 + l + 32 * i], a);
    #pragma unroll
    for (int off = 16; off; off >>= 1) a += __shfl_xor_sync(0xffffffff, a, off);
    if (l == 0) out[b * 10 + wrp] = a + b2[wrp];
}

// ---------------- launch ----------------
extern "C" void kernel_launch(void* const* d_in, const int* in_sizes, int n_in,
                              void* d_out, int out_size) {
    const float* x       = (const float*)d_in[0];
    const float* theta   = (const float*)d_in[1];
    const float* sigma   = (const float*)d_in[2];
    const float* gamma   = (const float*)d_in[3];
    const float* lambd   = (const float*)d_in[4];
    const float* psi     = (const float*)d_in[5];
    const float* conv2_w = (const float*)d_in[6];
    const float* conv2_b = (const float*)d_in[7];
    const float* fc1_w   = (const float*)d_in[8];
    const float* fc1_b   = (const float*)d_in[9];
    const float* fc2_w   = (const float*)d_in[10];
    const float* fc2_b   = (const float*)d_in[11];
    float* out = (float*)d_out;

    cudaFuncSetAttribute(k_conv2_mma, cudaFuncAttributeMaxDynamicSharedMemorySize, C2_SMEM);

    k_gabor<<<1, 288>>>(theta, sigma, gamma, lambd, psi);
    k_conv1<<<BATCH, 256>>>(x);
    k_conv2_mma<<<152, C2_THREADS, C2_SMEM>>>(conv2_w, conv2_b);
    dim3 g1(128, 7);
    k_fc1<<<g1, 128>>>(fc1_w);
    k_fc2<<<BATCH, 320>>>(fc2_w, fc1_b, fc2_b, out);
}

// round 12
// speedup vs baseline: 3.9555x; 1.3684x over previous
#include <cuda_runtime.h>
#include <cuda_fp16.h>
#include <cstdint>

#define BATCH 4096
#define PI2F  6.28318530717958647692f

typedef unsigned long long u64;

// ---------------- f32x2 helpers ----------------
__device__ __forceinline__ u64 pk2(float lo, float hi) {
    u64 r; asm("mov.b64 %0, {%1,%2};" : "=l"(r) : "f"(lo), "f"(hi)); return r;
}
__device__ __forceinline__ void upk2(u64 v, float& lo, float& hi) {
    asm("mov.b64 {%0,%1}, %2;" : "=f"(lo), "=f"(hi) : "l"(v));
}
__device__ __forceinline__ u64 fma2(u64 a, u64 b, u64 c) {
    u64 d; asm("fma.rn.f32x2 %0, %1, %2, %3;" : "=l"(d) : "l"(a), "l"(b), "l"(c)); return d;
}

// ---------------- HMMA m16n8k16 (f16 x f16 -> f32) ----------------
#define MMA16816(d, a0, a1, a2, a3, b0, b1) \
    asm volatile("mma.sync.aligned.m16n8k16.row.col.f32.f16.f16.f32 " \
        "{%0,%1,%2,%3}, {%4,%5,%6,%7}, {%8,%9}, {%0,%1,%2,%3};" \
        : "+f"((d)[0]), "+f"((d)[1]), "+f"((d)[2]), "+f"((d)[3]) \
        : "r"(a0), "r"(a1), "r"(a2), "r"(a3), "r"(b0), "r"(b1))

// ---------------- scratch ----------------
__device__ float  g_w1[32 * 9];
__device__ float  g_out1[BATCH * 32 * 14 * 14];
__device__ __half g_out2h[BATCH * 64 * 7 * 7];     // conv2 out, fp16
__device__ __half g_fw_hi[128 * 3136];             // fc1 weights split
__device__ __half g_fw_lo[128 * 3136];
__device__ float  g_fc1p[7][BATCH * 128];

// ---------------- kernel 0: gabor weights ----------------
__global__ void k_gabor(const float* __restrict__ theta, const float* __restrict__ sigma,
                        const float* __restrict__ gamma, const float* __restrict__ lambd,
                        const float* __restrict__ psi) {
    int t = threadIdx.x;
    if (t >= 288) return;
    int c = t / 9, idx = t % 9;
    int i = idx / 3, j = idx % 3;
    float val;
    if (c < 16) {
        float xg = (float)(i - 1), yg = (float)(j - 1);
        float th = theta[c];
        float cth = cosf(th), sth = sinf(th);
        float xt =  xg * cth + yg * sth;
        float yt = -xg * sth + yg * cth;
        float sx = sigma[c];
        float sy = sigma[c] / gamma[c];
        float env = expf(-0.5f * (xt * xt / (sx * sx) + yt * yt / (sy * sy)));
        float car = cosf(PI2F * xt / lambd[c] + psi[c]);
        val = env * car;
    } else {
        val = (idx == 4) ? 1.0f : 0.0f;
    }
    g_w1[c * 9 + idx] = val;
}

// ---------------- kernel 0b: split fc1 weights into fp16 hi+lo ----------------
__global__ void k_wcvt(const float* __restrict__ W) {
    int i = blockIdx.x * 256 + threadIdx.x;
    if (i >= 128 * 3136) return;
    float w = W[i];
    __half h = __float2half_rn(w);
    g_fw_hi[i] = h;
    g_fw_lo[i] = __float2half_rn(w - __half2float(h));
}

// ---------------- kernel 1: conv1 + relu + maxpool2, f32x2 channel pairs ----------------
__global__ void k_conv1(const float* __restrict__ x) {
    __shared__ float si[30 * 30];
    __shared__ float sw2[9 * 32];           // [q][c] so channel pairs are LDS.64
    int b = blockIdx.x;
    for (int i = threadIdx.x; i < 900; i += 256) si[i] = 0.0f;
    for (int i = threadIdx.x; i < 288; i += 256) {
        int c = i / 9, q = i % 9;
        sw2[q * 32 + c] = g_w1[i];
    }
    __syncthreads();
    for (int i = threadIdx.x; i < 784; i += 256) {
        int y = i / 28, xx = i % 28;
        si[(y + 1) * 30 + xx + 1] = x[b * 784 + i];
    }
    __syncthreads();

    for (int o = threadIdx.x; o < 16 * 196; o += 256) {
        int cp = o / 196, p = o % 196;       // channel pair (2cp, 2cp+1)
        int py = p / 14, px = p % 14;

        u64 w2[9];
        #pragma unroll
        for (int q = 0; q < 9; q++) w2[q] = *(const u64*)&sw2[q * 32 + 2 * cp];

        float rr[4][4];
        const float* sp = si + (2 * py) * 30 + 2 * px;
        #pragma unroll
        for (int r = 0; r < 4; r++)
            #pragma unroll
            for (int c = 0; c < 4; c++) rr[r][c] = sp[r * 30 + c];

        float m0 = 0.0f, m1 = 0.0f;
        #pragma unroll
        for (int dy = 0; dy < 2; dy++)
            #pragma unroll
            for (int dx = 0; dx < 2; dx++) {
                u64 a = 0ULL;
                #pragma unroll
                for (int ky = 0; ky < 3; ky++)
                    #pragma unroll
                    for (int kx = 0; kx < 3; kx++) {
                        float v = rr[dy + ky][dx + kx];
                        a = fma2(pk2(v, v), w2[ky * 3 + kx], a);
                    }
                float lo, hi; upk2(a, lo, hi);
                m0 = fmaxf(m0, lo);
                m1 = fmaxf(m1, hi);
            }
        g_out1[b * 6272 + (2 * cp) * 196 + p]     = m0;
        g_out1[b * 6272 + (2 * cp + 1) * 196 + p] = m1;
    }
}

// ---------------- kernel 2: conv2 via HMMA shift-decomposition ----------------
#define C2_THREADS 224
#define SM_BIAS 0
#define SM_IN   256                 // 292*36 halves = 21024 B
#define SM_W    21312               // 64*296 halves = 37888 B
#define SM_POOL 59264               // 224*66 floats = 59136 B
#define C2_SMEM 118400

__global__ void __launch_bounds__(C2_THREADS, 1)
k_conv2_mma(const float* __restrict__ w, const float* __restrict__ bias) {
    extern __shared__ char sm[];
    float* biasS = (float*)(sm + SM_BIAS);
    __half* wH   = (__half*)(sm + SM_W);
    float* pool  = (float*)(sm + SM_POOL);
    uint32_t* inw       = (uint32_t*)(sm + SM_IN);
    const uint32_t* ww  = (const uint32_t*)(sm + SM_W);
    int tid = threadIdx.x, warp = tid >> 5, lane = tid & 31;
    int grp = lane >> 2, tig = lane & 3;

    if (tid < 64) biasS[tid] = bias[tid];
    for (int i = tid; i < 292 * 18; i += C2_THREADS) inw[i] = 0u;
    for (int i = tid; i < 64 * 288; i += C2_THREADS) {
        int oc = i / 288, r = i % 288, ic = r / 9, q = r % 9;
        wH[oc * 296 + q * 32 + ic] = __float2half_rn(w[i]);
    }
    __syncthreads();

    int rb[4];
    {
        int t0 = 2 * warp;
        int ps[4] = { t0 * 16 + grp, t0 * 16 + grp + 8,
                      t0 * 16 + 16 + grp, t0 * 16 + 16 + grp + 8 };
        #pragma unroll
        for (int j = 0; j < 4; j++)
            rb[j] = (ps[j] < 196) ? ((ps[j] / 14) * 16 + (ps[j] % 14)) * 18
                                  : 256 * 18;
    }

    for (int img = blockIdx.x; img < BATCH; img += gridDim.x) {
        const float* src = g_out1 + img * 6272;
        for (int e = tid; e < 16 * 196; e += C2_THREADS) {
            int ic2 = e / 196, p = e % 196;
            float v0 = src[(2 * ic2) * 196 + p];
            float v1 = src[(2 * ic2 + 1) * 196 + p];
            int row = (p / 14 + 1) * 16 + (p % 14) + 1;
            uint32_t pk = (uint32_t)__half_as_ushort(__float2half_rn(v0))
                        | ((uint32_t)__half_as_ushort(__float2half_rn(v1)) << 16);
            inw[row * 18 + ic2] = pk;
        }
        __syncthreads();

        if (warp < 7) {
            float acc[2][8][4];
            #pragma unroll
            for (int ti = 0; ti < 2; ti++)
                #pragma unroll
                for (int nt = 0; nt < 8; nt++)
                    #pragma unroll
                    for (int q = 0; q < 4; q++) acc[ti][nt][q] = 0.0f;

            #pragma unroll 1
            for (int ky = 0; ky < 3; ky++) {
                #pragma unroll 1
                for (int kx = 0; kx < 3; kx++) {
                    int sh = (ky * 16 + kx) * 18;
                    int wq = (ky * 3 + kx) * 16;
                    #pragma unroll
                    for (int s = 0; s < 2; s++) {
                        int ao = sh + s * 8 + tig;
                        uint32_t a0 = inw[rb[0] + ao];
                        uint32_t a1 = inw[rb[1] + ao];
                        uint32_t a2 = inw[rb[0] + ao + 4];
                        uint32_t a3 = inw[rb[1] + ao + 4];
                        uint32_t a4 = inw[rb[2] + ao];
                        uint32_t a5 = inw[rb[3] + ao];
                        uint32_t a6 = inw[rb[2] + ao + 4];
                        uint32_t a7 = inw[rb[3] + ao + 4];
                        int wo = wq + s * 8 + tig;
                        uint32_t bA[8], bB[8];
                        #pragma unroll
                        for (int nt = 0; nt < 8; nt++) {
                            int n = nt * 8 + grp;
                            bA[nt] = ww[n * 148 + wo];
                            bB[nt] = ww[n * 148 + wo + 4];
                        }
                        #pragma unroll
                        for (int nt = 0; nt < 8; nt++) {
                            MMA16816(acc[0][nt], a0, a1, a2, a3, bA[nt], bB[nt]);
                            MMA16816(acc[1][nt], a4, a5, a6, a7, bA[nt], bB[nt]);
                        }
                    }
                }
            }

            #pragma unroll
            for (int ti = 0; ti < 2; ti++) {
                int pr0 = (2 * warp + ti) * 16 + grp;
                #pragma unroll
                for (int nt = 0; nt < 8; nt++) {
                    int cb = nt * 8 + 2 * tig;
                    *(float2*)&pool[pr0 * 66 + cb]       = make_float2(acc[ti][nt][0], acc[ti][nt][1]);
                    *(float2*)&pool[(pr0 + 8) * 66 + cb] = make_float2(acc[ti][nt][2], acc[ti][nt][3]);
                }
            }
        }
        __syncthreads();

        // ---- bias + relu + 2x2 maxpool -> g_out2h (fp16) ----
        __half* dst = g_out2h + (u64)img * 3136;
        for (int e = tid; e < 3136; e += C2_THREADS) {
            int oc = e / 49, pq = e % 49;
            int py = pq / 7, px = pq % 7;
            int p00 = (2 * py) * 14 + 2 * px;
            float m = fmaxf(fmaxf(pool[p00 * 66 + oc],        pool[(p00 + 1) * 66 + oc]),
                            fmaxf(pool[(p00 + 14) * 66 + oc], pool[(p00 + 15) * 66 + oc]));
            dst[oc * 49 + pq] = __float2half_rn(fmaxf(m + biasS[oc], 0.0f));
        }
        __syncthreads();
    }
}

// ---------------- kernel 3: fc1 via HMMA, split-fp16 weights ----------------
// grid (32, 7): BM=128, full N=128, K-chunk 448. 8 warps = 2M x 4N, warp tile 64x32.
#define F1_SMEM (3 * 128 * 72 * 2)   // A + B_hi + B_lo tiles, 55296 B

__global__ void __launch_bounds__(256, 1)
k_fc1_mma() {
    extern __shared__ __half sh[];
    __half* aS  = sh;                  // [128][72]
    __half* bhS = sh + 128 * 72;
    __half* blS = sh + 2 * 128 * 72;
    int tid = threadIdx.x, warp = tid >> 5, lane = tid & 31;
    int grp = lane >> 2, tig = lane & 3;
    int bm   = blockIdx.x * 128;
    int koff = blockIdx.y * 448;
    int wm = warp & 1, wn = warp >> 1;

    float acc[4][4][4];
    #pragma unroll
    for (int mt = 0; mt < 4; mt++)
        #pragma unroll
        for (int nt = 0; nt < 4; nt++)
            #pragma unroll
            for (int q = 0; q < 4; q++) acc[mt][nt][q] = 0.0f;

    const __half* Ag  = g_out2h + (u64)bm * 3136 + koff;
    const __half* Bhg = g_fw_hi + koff;
    const __half* Blg = g_fw_lo + koff;

    for (int k0 = 0; k0 < 448; k0 += 64) {
        #pragma unroll
        for (int i = 0; i < 4; i++) {
            int idx = tid + i * 256;
            int row = idx >> 3, c8 = (idx & 7) * 8;
            *(uint4*)&aS[row * 72 + c8]  = *(const uint4*)&Ag[(u64)row * 3136 + k0 + c8];
            *(uint4*)&bhS[row * 72 + c8] = *(const uint4*)&Bhg[(u64)row * 3136 + k0 + c8];
            *(uint4*)&blS[row * 72 + c8] = *(const uint4*)&Blg[(u64)row * 3136 + k0 + c8];
        }
        __syncthreads();

        #pragma unroll
        for (int ks = 0; ks < 4; ks++) {
            uint32_t af[4][4];
            #pragma unroll
            for (int mt = 0; mt < 4; mt++) {
                int rm = wm * 64 + mt * 16 + grp;
                const uint32_t* pa  = (const uint32_t*)&aS[rm * 72 + ks * 16 + tig * 2];
                const uint32_t* pa8 = (const uint32_t*)&aS[(rm + 8) * 72 + ks * 16 + tig * 2];
                af[mt][0] = pa[0];  af[mt][1] = pa8[0];
                af[mt][2] = pa[4];  af[mt][3] = pa8[4];
            }
            #pragma unroll
            for (int nt = 0; nt < 4; nt++) {
                int n = wn * 32 + nt * 8 + grp;
                const uint32_t* pbh = (const uint32_t*)&bhS[n * 72 + ks * 16 + tig * 2];
                const uint32_t* pbl = (const uint32_t*)&blS[n * 72 + ks * 16 + tig * 2];
                uint32_t bh0 = pbh[0], bh1 = pbh[4];
                uint32_t bl0 = pbl[0], bl1 = pbl[4];
                #pragma unroll
                for (int mt = 0; mt < 4; mt++) {
                    MMA16816(acc[mt][nt], af[mt][0], af[mt][1], af[mt][2], af[mt][3], bh0, bh1);
                    MMA16816(acc[mt][nt], af[mt][0], af[mt][1], af[mt][2], af[mt][3], bl0, bl1);
                }
            }
        }
        __syncthreads();
    }

    float* outp = &g_fc1p[blockIdx.y][0];
    #pragma unroll
    for (int mt = 0; mt < 4; mt++) {
        int row = bm + wm * 64 + mt * 16 + grp;
        #pragma unroll
        for (int nt = 0; nt < 4; nt++) {
            int col = wn * 32 + nt * 8 + 2 * tig;
            *(float2*)&outp[row * 128 + col]       = make_float2(acc[mt][nt][0], acc[mt][nt][1]);
            *(float2*)&outp[(row + 8) * 128 + col] = make_float2(acc[mt][nt][2], acc[mt][nt][3]);
        }
    }
}

// ---------------- kernel 4: combine 7 partials + bias + relu + fc2 ----------------
__global__ void k_fc2(const float* __restrict__ W2, const float* __restrict__ fc1b,
                      const float* __restrict__ b2, float* __restrict__ out) {
    __shared__ float h[128];
    __shared__ float sw[1280];
    int b = blockIdx.x, tid = threadIdx.x;
    for (int i = tid; i < 1280; i += 320) sw[i] = W2[i];
    if (tid < 128) {
        float s = fc1b[tid];
        #pragma unroll
        for (int sp = 0; sp < 7; sp++) s += g_fc1p[sp][b * 128 + tid];
        h[tid] = fmaxf(s, 0.0f);
    }
    __syncthreads();
    int wrp = tid / 32, l = tid % 32;
    float a = 0.0f;
    #pragma unroll
    for (int i = 0; i < 4; i++) a = fmaf(h[l + 32 * i], sw[wrp * 128 + l + 32 * i], a);
    #pragma unroll
    for (int off = 16; off; off >>= 1) a += __shfl_xor_sync(0xffffffff, a, off);
    if (l == 0) out[b * 10 + wrp] = a + b2[wrp];
}

// ---------------- launch ----------------
extern "C" void kernel_launch(void* const* d_in, const int* in_sizes, int n_in,
                              void* d_out, int out_size) {
    const float* x       = (const float*)d_in[0];
    const float* theta   = (const float*)d_in[1];
    const float* sigma   = (const float*)d_in[2];
    const float* gamma   = (const float*)d_in[3];
    const float* lambd   = (const float*)d_in[4];
    const float* psi     = (const float*)d_in[5];
    const float* conv2_w = (const float*)d_in[6];
    const float* conv2_b = (const float*)d_in[7];
    const float* fc1_w   = (const float*)d_in[8];
    const float* fc1_b   = (const float*)d_in[9];
    const float* fc2_w   = (const float*)d_in[10];
    const float* fc2_b   = (const float*)d_in[11];
    float* out = (float*)d_out;

    cudaFuncSetAttribute(k_conv2_mma, cudaFuncAttributeMaxDynamicSharedMemorySize, C2_SMEM);
    cudaFuncSetAttribute(k_fc1_mma,  cudaFuncAttributeMaxDynamicSharedMemorySize, F1_SMEM);

    k_gabor<<<1, 288>>>(theta, sigma, gamma, lambd, psi);
    k_wcvt<<<(128 * 3136 + 255) / 256, 256>>>(fc1_w);
    k_conv1<<<BATCH, 256>>>(x);
    k_conv2_mma<<<152, C2_THREADS, C2_SMEM>>>(conv2_w, conv2_b);
    dim3 g1(32, 7);
    k_fc1_mma<<<g1, 256, F1_SMEM>>>();
    k_fc2<<<BATCH, 320>>>(fc2_w, fc1_b, fc2_b, out);
}

// round 13
// speedup vs baseline: 5.4554x; 1.3792x over previous
#include <cuda_runtime.h>
#include <cuda_fp16.h>
#include <cstdint>

#define BATCH 4096
#define PI2F  6.28318530717958647692f

typedef unsigned long long u64;

// ---------------- f32x2 helpers ----------------
__device__ __forceinline__ u64 pk2(float lo, float hi) {
    u64 r; asm("mov.b64 %0, {%1,%2};" : "=l"(r) : "f"(lo), "f"(hi)); return r;
}
__device__ __forceinline__ void upk2(u64 v, float& lo, float& hi) {
    asm("mov.b64 {%0,%1}, %2;" : "=f"(lo), "=f"(hi) : "l"(v));
}
__device__ __forceinline__ u64 fma2(u64 a, u64 b, u64 c) {
    u64 d; asm("fma.rn.f32x2 %0, %1, %2, %3;" : "=l"(d) : "l"(a), "l"(b), "l"(c)); return d;
}

// ---------------- HMMA m16n8k16 (f16 x f16 -> f32) ----------------
#define MMA16816(d, a0, a1, a2, a3, b0, b1) \
    asm volatile("mma.sync.aligned.m16n8k16.row.col.f32.f16.f16.f32 " \
        "{%0,%1,%2,%3}, {%4,%5,%6,%7}, {%8,%9}, {%0,%1,%2,%3};" \
        : "+f"((d)[0]), "+f"((d)[1]), "+f"((d)[2]), "+f"((d)[3]) \
        : "r"(a0), "r"(a1), "r"(a2), "r"(a3), "r"(b0), "r"(b1))

// ---------------- scratch ----------------
__device__ float    g_w1[32 * 9];
__device__ uint32_t g_out1h[BATCH * 196 * 16];     // conv1 out: [img][pos][ch-pair] packed half2
__device__ __half   g_out2h[BATCH * 64 * 7 * 7];   // conv2 out, fp16
__device__ __half   g_fw_hi[128 * 3136];           // fc1 weights split
__device__ __half   g_fw_lo[128 * 3136];
__device__ float    g_fc1p[7][BATCH * 128];

// ---------------- kernel 0: gabor weights ----------------
__global__ void k_gabor(const float* __restrict__ theta, const float* __restrict__ sigma,
                        const float* __restrict__ gamma, const float* __restrict__ lambd,
                        const float* __restrict__ psi) {
    int t = threadIdx.x;
    if (t >= 288) return;
    int c = t / 9, idx = t % 9;
    int i = idx / 3, j = idx % 3;
    float val;
    if (c < 16) {
        float xg = (float)(i - 1), yg = (float)(j - 1);
        float th = theta[c];
        float cth = cosf(th), sth = sinf(th);
        float xt =  xg * cth + yg * sth;
        float yt = -xg * sth + yg * cth;
        float sx = sigma[c];
        float sy = sigma[c] / gamma[c];
        float env = expf(-0.5f * (xt * xt / (sx * sx) + yt * yt / (sy * sy)));
        float car = cosf(PI2F * xt / lambd[c] + psi[c]);
        val = env * car;
    } else {
        val = (idx == 4) ? 1.0f : 0.0f;
    }
    g_w1[c * 9 + idx] = val;
}

// ---------------- kernel 0b: split fc1 weights into fp16 hi+lo ----------------
__global__ void k_wcvt(const float* __restrict__ W) {
    int i = blockIdx.x * 256 + threadIdx.x;
    if (i >= 128 * 3136) return;
    float w = W[i];
    __half h = __float2half_rn(w);
    g_fw_hi[i] = h;
    g_fw_lo[i] = __float2half_rn(w - __half2float(h));
}

// ---------------- kernel 1: conv1 + relu + maxpool2 -> packed fp16 HWC pairs ----------------
__global__ void k_conv1(const float* __restrict__ x) {
    __shared__ float si[30 * 30];
    __shared__ float sw2[9 * 32];           // [q][c] so channel pairs are LDS.64
    int b = blockIdx.x;
    for (int i = threadIdx.x; i < 900; i += 256) si[i] = 0.0f;
    for (int i = threadIdx.x; i < 288; i += 256) {
        int c = i / 9, q = i % 9;
        sw2[q * 32 + c] = g_w1[i];
    }
    __syncthreads();
    for (int i = threadIdx.x; i < 784; i += 256) {
        int y = i / 28, xx = i % 28;
        si[(y + 1) * 30 + xx + 1] = x[b * 784 + i];
    }
    __syncthreads();

    // o = p*16 + cp  -> coalesced packed writes
    for (int o = threadIdx.x; o < 196 * 16; o += 256) {
        int cp = o & 15, p = o >> 4;
        int py = p / 14, px = p % 14;

        u64 w2[9];
        #pragma unroll
        for (int q = 0; q < 9; q++) w2[q] = *(const u64*)&sw2[q * 32 + 2 * cp];

        float rr[4][4];
        const float* sp = si + (2 * py) * 30 + 2 * px;
        #pragma unroll
        for (int r = 0; r < 4; r++)
            #pragma unroll
            for (int c = 0; c < 4; c++) rr[r][c] = sp[r * 30 + c];

        float m0 = 0.0f, m1 = 0.0f;
        #pragma unroll
        for (int dy = 0; dy < 2; dy++)
            #pragma unroll
            for (int dx = 0; dx < 2; dx++) {
                u64 a = 0ULL;
                #pragma unroll
                for (int ky = 0; ky < 3; ky++)
                    #pragma unroll
                    for (int kx = 0; kx < 3; kx++) {
                        float v = rr[dy + ky][dx + kx];
                        a = fma2(pk2(v, v), w2[ky * 3 + kx], a);
                    }
                float lo, hi; upk2(a, lo, hi);
                m0 = fmaxf(m0, lo);
                m1 = fmaxf(m1, hi);
            }
        uint32_t pk = (uint32_t)__half_as_ushort(__float2half_rn(m0))
                    | ((uint32_t)__half_as_ushort(__float2half_rn(m1)) << 16);
        g_out1h[b * 3136 + o] = pk;
    }
}

// ---------------- kernel 2: conv2 via HMMA shift-decomposition (2 CTAs/SM) ----------------
// Input as padded HWC fp16 [292 rows][36 halves]. 3x3 conv = 9 shifted GEMMs of K=32.
// W fp16 [64 oc][296 halves]. 7 compute warps: warp w owns M-tiles 2w,2w+1 x 8 n8-tiles.
#define C2_THREADS 224
#define SM_BIAS 0
#define SM_IN   256                 // 292*36 halves = 21024 B
#define SM_W    21312               // 64*296 halves = 37888 B
#define SM_POOL 59200               // 196*66 floats = 51744 B
#define C2_SMEM 110944

__global__ void __launch_bounds__(C2_THREADS, 2)
k_conv2_mma(const float* __restrict__ w, const float* __restrict__ bias) {
    extern __shared__ char sm[];
    float* biasS = (float*)(sm + SM_BIAS);
    __half* wH   = (__half*)(sm + SM_W);
    float* pool  = (float*)(sm + SM_POOL);
    uint32_t* inw       = (uint32_t*)(sm + SM_IN);
    const uint32_t* ww  = (const uint32_t*)(sm + SM_W);
    int tid = threadIdx.x, warp = tid >> 5, lane = tid & 31;
    int grp = lane >> 2, tig = lane & 3;

    if (tid < 64) biasS[tid] = bias[tid];
    for (int i = tid; i < 292 * 18; i += C2_THREADS) inw[i] = 0u;
    for (int i = tid; i < 64 * 288; i += C2_THREADS) {
        int oc = i / 288, r = i % 288, ic = r / 9, q = r % 9;
        wH[oc * 296 + q * 32 + ic] = __float2half_rn(w[i]);
    }
    __syncthreads();

    int rb[4];
    {
        int t0 = 2 * warp;
        int ps[4] = { t0 * 16 + grp, t0 * 16 + grp + 8,
                      t0 * 16 + 16 + grp, t0 * 16 + 16 + grp + 8 };
        #pragma unroll
        for (int j = 0; j < 4; j++)
            rb[j] = (ps[j] < 196) ? ((ps[j] / 14) * 16 + (ps[j] % 14)) * 18
                                  : 256 * 18;
    }

    for (int img = blockIdx.x; img < BATCH; img += gridDim.x) {
        // ---- coalesced copy: packed HWC pairs -> padded rows ----
        const uint32_t* src = g_out1h + (u64)img * 3136;
        for (int e = tid; e < 3136; e += C2_THREADS) {
            int p = e >> 4, cp = e & 15;
            int row = (p / 14 + 1) * 16 + (p % 14) + 1;
            inw[row * 18 + cp] = src[e];
        }
        __syncthreads();

        if (warp < 7) {
            float acc[2][8][4];
            #pragma unroll
            for (int ti = 0; ti < 2; ti++)
                #pragma unroll
                for (int nt = 0; nt < 8; nt++)
                    #pragma unroll
                    for (int q = 0; q < 4; q++) acc[ti][nt][q] = 0.0f;

            #pragma unroll 1
            for (int ky = 0; ky < 3; ky++) {
                #pragma unroll 1
                for (int kx = 0; kx < 3; kx++) {
                    int sh = (ky * 16 + kx) * 18;
                    int wq = (ky * 3 + kx) * 16;
                    #pragma unroll
                    for (int s = 0; s < 2; s++) {
                        int ao = sh + s * 8 + tig;
                        uint32_t a0 = inw[rb[0] + ao];
                        uint32_t a1 = inw[rb[1] + ao];
                        uint32_t a2 = inw[rb[0] + ao + 4];
                        uint32_t a3 = inw[rb[1] + ao + 4];
                        uint32_t a4 = inw[rb[2] + ao];
                        uint32_t a5 = inw[rb[3] + ao];
                        uint32_t a6 = inw[rb[2] + ao + 4];
                        uint32_t a7 = inw[rb[3] + ao + 4];
                        int wo = wq + s * 8 + tig;
                        uint32_t bA[8], bB[8];
                        #pragma unroll
                        for (int nt = 0; nt < 8; nt++) {
                            int n = nt * 8 + grp;
                            bA[nt] = ww[n * 148 + wo];
                            bB[nt] = ww[n * 148 + wo + 4];
                        }
                        #pragma unroll
                        for (int nt = 0; nt < 8; nt++) {
                            MMA16816(acc[0][nt], a0, a1, a2, a3, bA[nt], bB[nt]);
                            MMA16816(acc[1][nt], a4, a5, a6, a7, bA[nt], bB[nt]);
                        }
                    }
                }
            }

            // ---- D frags -> pool smem [pos<196][66] ----
            #pragma unroll
            for (int ti = 0; ti < 2; ti++) {
                int pr0 = (2 * warp + ti) * 16 + grp;
                #pragma unroll
                for (int nt = 0; nt < 8; nt++) {
                    int cb = nt * 8 + 2 * tig;
                    if (pr0 < 196)
                        *(float2*)&pool[pr0 * 66 + cb] = make_float2(acc[ti][nt][0], acc[ti][nt][1]);
                    if (pr0 + 8 < 196)
                        *(float2*)&pool[(pr0 + 8) * 66 + cb] = make_float2(acc[ti][nt][2], acc[ti][nt][3]);
                }
            }
        }
        __syncthreads();

        // ---- bias + relu + 2x2 maxpool -> g_out2h (fp16) ----
        __half* dst = g_out2h + (u64)img * 3136;
        for (int e = tid; e < 3136; e += C2_THREADS) {
            int oc = e / 49, pq = e % 49;
            int py = pq / 7, px = pq % 7;
            int p00 = (2 * py) * 14 + 2 * px;
            float m = fmaxf(fmaxf(pool[p00 * 66 + oc],        pool[(p00 + 1) * 66 + oc]),
                            fmaxf(pool[(p00 + 14) * 66 + oc], pool[(p00 + 15) * 66 + oc]));
            dst[oc * 49 + pq] = __float2half_rn(fmaxf(m + biasS[oc], 0.0f));
        }
        __syncthreads();
    }
}

// ---------------- kernel 3: fc1 via HMMA, split-fp16 weights ----------------
// grid (32, 7): BM=128, full N=128, K-chunk 448. 8 warps = 2M x 4N, warp tile 64x32.
#define F1_SMEM (3 * 128 * 72 * 2)   // A + B_hi + B_lo tiles, 55296 B

__global__ void __launch_bounds__(256, 1)
k_fc1_mma() {
    extern __shared__ __half sh[];
    __half* aS  = sh;                  // [128][72]
    __half* bhS = sh + 128 * 72;
    __half* blS = sh + 2 * 128 * 72;
    int tid = threadIdx.x, warp = tid >> 5, lane = tid & 31;
    int grp = lane >> 2, tig = lane & 3;
    int bm   = blockIdx.x * 128;
    int koff = blockIdx.y * 448;
    int wm = warp & 1, wn = warp >> 1;

    float acc[4][4][4];
    #pragma unroll
    for (int mt = 0; mt < 4; mt++)
        #pragma unroll
        for (int nt = 0; nt < 4; nt++)
            #pragma unroll
            for (int q = 0; q < 4; q++) acc[mt][nt][q] = 0.0f;

    const __half* Ag  = g_out2h + (u64)bm * 3136 + koff;
    const __half* Bhg = g_fw_hi + koff;
    const __half* Blg = g_fw_lo + koff;

    for (int k0 = 0; k0 < 448; k0 += 64) {
        #pragma unroll
        for (int i = 0; i < 4; i++) {
            int idx = tid + i * 256;
            int row = idx >> 3, c8 = (idx & 7) * 8;
            *(uint4*)&aS[row * 72 + c8]  = *(const uint4*)&Ag[(u64)row * 3136 + k0 + c8];
            *(uint4*)&bhS[row * 72 + c8] = *(const uint4*)&Bhg[(u64)row * 3136 + k0 + c8];
            *(uint4*)&blS[row * 72 + c8] = *(const uint4*)&Blg[(u64)row * 3136 + k0 + c8];
        }
        __syncthreads();

        #pragma unroll
        for (int ks = 0; ks < 4; ks++) {
            uint32_t af[4][4];
            #pragma unroll
            for (int mt = 0; mt < 4; mt++) {
                int rm = wm * 64 + mt * 16 + grp;
                const uint32_t* pa  = (const uint32_t*)&aS[rm * 72 + ks * 16 + tig * 2];
                const uint32_t* pa8 = (const uint32_t*)&aS[(rm + 8) * 72 + ks * 16 + tig * 2];
                af[mt][0] = pa[0];  af[mt][1] = pa8[0];
                af[mt][2] = pa[4];  af[mt][3] = pa8[4];
            }
            #pragma unroll
            for (int nt = 0; nt < 4; nt++) {
                int n = wn * 32 + nt * 8 + grp;
                const uint32_t* pbh = (const uint32_t*)&bhS[n * 72 + ks * 16 + tig * 2];
                const uint32_t* pbl = (const uint32_t*)&blS[n * 72 + ks * 16 + tig * 2];
                uint32_t bh0 = pbh[0], bh1 = pbh[4];
                uint32_t bl0 = pbl[0], bl1 = pbl[4];
                #pragma unroll
                for (int mt = 0; mt < 4; mt++) {
                    MMA16816(acc[mt][nt], af[mt][0], af[mt][1], af[mt][2], af[mt][3], bh0, bh1);
                    MMA16816(acc[mt][nt], af[mt][0], af[mt][1], af[mt][2], af[mt][3], bl0, bl1);
                }
            }
        }
        __syncthreads();
    }

    float* outp = &g_fc1p[blockIdx.y][0];
    #pragma unroll
    for (int mt = 0; mt < 4; mt++) {
        int row = bm + wm * 64 + mt * 16 + grp;
        #pragma unroll
        for (int nt = 0; nt < 4; nt++) {
            int col = wn * 32 + nt * 8 + 2 * tig;
            *(float2*)&outp[row * 128 + col]       = make_float2(acc[mt][nt][0], acc[mt][nt][1]);
            *(float2*)&outp[(row + 8) * 128 + col] = make_float2(acc[mt][nt][2], acc[mt][nt][3]);
        }
    }
}

// ---------------- kernel 4: combine 7 partials + bias + relu + fc2 ----------------
__global__ void k_fc2(const float* __restrict__ W2, const float* __restrict__ fc1b,
                      const float* __restrict__ b2, float* __restrict__ out) {
    __shared__ float h[128];
    __shared__ float sw[1280];
    int b = blockIdx.x, tid = threadIdx.x;
    for (int i = tid; i < 1280; i += 320) sw[i] = W2[i];
    if (tid < 128) {
        float s = fc1b[tid];
        #pragma unroll
        for (int sp = 0; sp < 7; sp++) s += g_fc1p[sp][b * 128 + tid];
        h[tid] = fmaxf(s, 0.0f);
    }
    __syncthreads();
    int wrp = tid / 32, l = tid % 32;
    float a = 0.0f;
    #pragma unroll
    for (int i = 0; i < 4; i++) a = fmaf(h[l + 32 * i], sw[wrp * 128 + l + 32 * i], a);
    #pragma unroll
    for (int off = 16; off; off >>= 1) a += __shfl_xor_sync(0xffffffff, a, off);
    if (l == 0) out[b * 10 + wrp] = a + b2[wrp];
}

// ---------------- launch ----------------
extern "C" void kernel_launch(void* const* d_in, const int* in_sizes, int n_in,
                              void* d_out, int out_size) {
    const float* x       = (const float*)d_in[0];
    const float* theta   = (const float*)d_in[1];
    const float* sigma   = (const float*)d_in[2];
    const float* gamma   = (const float*)d_in[3];
    const float* lambd   = (const float*)d_in[4];
    const float* psi     = (const float*)d_in[5];
    const float* conv2_w = (const float*)d_in[6];
    const float* conv2_b = (const float*)d_in[7];
    const float* fc1_w   = (const float*)d_in[8];
    const float* fc1_b   = (const float*)d_in[9];
    const float* fc2_w   = (const float*)d_in[10];
    const float* fc2_b   = (const float*)d_in[11];
    float* out = (float*)d_out;

    cudaFuncSetAttribute(k_conv2_mma, cudaFuncAttributeMaxDynamicSharedMemorySize, C2_SMEM);
    cudaFuncSetAttribute(k_fc1_mma,  cudaFuncAttributeMaxDynamicSharedMemorySize, F1_SMEM);

    k_gabor<<<1, 288>>>(theta, sigma, gamma, lambd, psi);
    k_wcvt<<<(128 * 3136 + 255) / 256, 256>>>(fc1_w);
    k_conv1<<<BATCH, 256>>>(x);
    k_conv2_mma<<<304, C2_THREADS, C2_SMEM>>>(conv2_w, conv2_b);
    dim3 g1(32, 7);
    k_fc1_mma<<<g1, 256, F1_SMEM>>>();
    k_fc2<<<BATCH, 320>>>(fc2_w, fc1_b, fc2_b, out);
}